// round 13
// baseline (speedup 1.0000x reference)
#include <cuda_runtime.h>
#include <cuda_fp16.h>
#include <cstdint>

#define S_ 1024
#define B_ 8
#define H_ 1024
#define T_ 8192
#define E_ 8
#define F_ 4096
#define NASSIGN (T_*2)
#define MAXROWS (NASSIGN + E_*128)
#define MAXTILES (MAXROWS/128)

// GEMM tiling: CTA 128x128, 8 warps x (64x32), K-chunk 64, 3-stage cp.async
#define KC 64
#define AST 144
#define TILEB (128*AST)
#define NSTAGE 3
#define SMEMSZ (NSTAGE*2*TILEB)   // 110592

// ---- static device scratch ----
__device__ __half g_w1t[(size_t)E_*F_*H_];   // [e][f][h] fp16, k-major rows
__device__ __half g_w2t[(size_t)E_*H_*F_];   // [e][h][f] fp16, k-major rows
__device__ __half g_xh[(size_t)MAXROWS*H_];
__device__ __half g_hbuf[(size_t)MAXROWS*F_];
__device__ float  g_y[(size_t)MAXROWS*H_];
__device__ int g_tileExpert[MAXTILES];
__device__ int g_rowToken[MAXROWS];
__device__ int g_posOf[NASSIGN];

__device__ __forceinline__ uint32_t smem_u32(const void* p){
    uint32_t a; asm("{ .reg .u64 t; cvta.to.shared.u64 t, %1; cvt.u32.u64 %0, t; }":"=r"(a):"l"(p)); return a;
}
__device__ __forceinline__ void cp16(uint32_t d, const void* s){
    asm volatile("cp.async.cg.shared.global [%0], [%1], 16;"::"r"(d),"l"(s):"memory");
}
#define CP_COMMIT() asm volatile("cp.async.commit_group;":::"memory")
#define CP_WAIT(n)  asm volatile("cp.async.wait_group %0;"::"n"(n):"memory")

__device__ __forceinline__ void ldm4(uint32_t* r, uint32_t addr){
    asm volatile("ldmatrix.sync.aligned.m8n8.x4.shared.b16 {%0,%1,%2,%3}, [%4];"
        : "=r"(r[0]),"=r"(r[1]),"=r"(r[2]),"=r"(r[3]) : "r"(addr));
}
// fp16-accumulate mma: C/D are 2 packed half2 regs
__device__ __forceinline__ void mma16816h(uint32_t* c, const uint32_t* a, uint32_t b0, uint32_t b1){
    asm volatile("mma.sync.aligned.m16n8k16.row.col.f16.f16.f16.f16 "
        "{%0,%1},{%2,%3,%4,%5},{%6,%7},{%0,%1};"
        : "+r"(c[0]),"+r"(c[1])
        : "r"(a[0]),"r"(a[1]),"r"(a[2]),"r"(a[3]),"r"(b0),"r"(b1));
}

// ---- fused routing (single block) ----
__global__ void __launch_bounds__(1024) k_route(const void* __restrict__ ce){
    __shared__ int scount[E_], scursor[E_], sbase[E_];
    __shared__ int sis32;
    const int tid = threadIdx.x;
    if (tid < E_){ scount[tid]=0; scursor[tid]=0; }
    if (tid == 0) sis32 = 0;
    for (int i = tid; i < MAXROWS; i += 1024) g_rowToken[i] = -1;
    __syncthreads();
    const long long* c64 = (const long long*)ce;
    for (int a = tid; a < NASSIGN/2; a += 1024){
        long long v = c64[a];
        if (v < 0 || v >= E_) sis32 = 1;
    }
    __syncthreads();
    const int is32 = sis32;
    for (int a = tid; a < NASSIGN; a += 1024){
        int e = is32 ? ((const int*)ce)[a] : (int)c64[a];
        atomicAdd(&scount[e], 1);
    }
    __syncthreads();
    if (tid == 0){
        int acc = 0;
        for (int e = 0; e < E_; e++){ sbase[e] = acc; acc += ((scount[e]+127)/128)*128; }
        int t = 0;
        for (int e = 0; e < E_; e++){
            int nt = (scount[e]+127)/128;
            for (int i = 0; i < nt && t < MAXTILES; i++) g_tileExpert[t++] = e;
        }
        for (; t < MAXTILES; t++) g_tileExpert[t] = -1;
    }
    __syncthreads();
    for (int a = tid; a < NASSIGN; a += 1024){
        int e = is32 ? ((const int*)ce)[a] : (int)c64[a];
        int pos = sbase[e] + atomicAdd(&scursor[e], 1);
        g_rowToken[pos] = a >> 1;
        g_posOf[a] = pos;
    }
}

__global__ void k_gather(const float* __restrict__ x){
    int pos = blockIdx.x;
    int tok = g_rowToken[pos];
    if (tok < 0) return;
    const float4* s = (const float4*)(x + (size_t)tok*H_);
    __half2* d = (__half2*)(g_xh + (size_t)pos*H_);
    float4 v = s[threadIdx.x];
    d[2*threadIdx.x]   = __floats2half2_rn(v.x, v.y);
    d[2*threadIdx.x+1] = __floats2half2_rn(v.z, v.w);
}

// fast transpose+convert: 64(row-in) x 32(col-in) tile, half2 packed stores
__global__ void k_w1t(const float* __restrict__ w1){
    __shared__ float t[64][33];
    int e = blockIdx.z, hb = blockIdx.y*64, fb = blockIdx.x*32;
    const float* src = w1 + (size_t)e*H_*F_;
    #pragma unroll
    for (int i = threadIdx.y; i < 64; i += 8)
        t[i][threadIdx.x] = src[(size_t)(hb+i)*F_ + fb + threadIdx.x];
    __syncthreads();
    __half2* dst = (__half2*)(g_w1t + (size_t)e*F_*H_);
    #pragma unroll
    for (int i = threadIdx.y; i < 32; i += 8){
        __half2 v = __floats2half2_rn(t[2*threadIdx.x][i], t[2*threadIdx.x+1][i]);
        dst[((size_t)(fb+i)*H_ + hb)/2 + threadIdx.x] = v;
    }
}
__global__ void k_w2t(const float* __restrict__ w2){
    __shared__ float t[64][33];
    int e = blockIdx.z, fb = blockIdx.y*64, hb = blockIdx.x*32;
    const float* src = w2 + (size_t)e*F_*H_;
    #pragma unroll
    for (int i = threadIdx.y; i < 64; i += 8)
        t[i][threadIdx.x] = src[(size_t)(fb+i)*H_ + hb + threadIdx.x];
    __syncthreads();
    __half2* dst = (__half2*)(g_w2t + (size_t)e*H_*F_);
    #pragma unroll
    for (int i = threadIdx.y; i < 32; i += 8){
        __half2 v = __floats2half2_rn(t[2*threadIdx.x][i], t[2*threadIdx.x+1][i]);
        dst[((size_t)(hb+i)*F_ + fb)/2 + threadIdx.x] = v;
    }
}

__device__ __forceinline__ float gelu_f(float v){
    float c = v + 0.044715f*v*v*v;
    return 0.5f*v*(1.0f + tanhf(0.7978845608028654f*c));
}

// ---- grouped GEMM: fp16-acc mma, promote to fp32 once per K=64 chunk ----
template<bool G1>
__global__ void __launch_bounds__(256, 2) k_gemm(){
    constexpr int Kd = G1 ? H_ : F_;
    constexpr int Nd = G1 ? F_ : H_;
    constexpr int NC = Kd/KC;
    extern __shared__ char smem[];
    const int tile_n = blockIdx.x, tile_m = blockIdx.y;
    const int e = g_tileExpert[tile_m];
    if (e < 0) return;
    const __half* A = G1 ? g_xh : g_hbuf;
    const __half* Bt = (G1 ? g_w1t : g_w2t) + (size_t)e*Nd*Kd;
    const int tid = threadIdx.x, wid = tid>>5, lane = tid&31;
    const int wm = wid & 1, wn = wid >> 1;
    const uint32_t sA = smem_u32(smem);
    const int rowA0 = tile_m*128, colB0 = tile_n*128;

    auto loadChunk = [&](int c, int st){
        const int kb = c*KC;
        const uint32_t base = sA + st*2*TILEB;
        #pragma unroll
        for (int i = 0; i < 4; i++){
            int idx = i*256 + tid;
            int row = idx >> 3, seg = idx & 7;
            cp16(base + row*AST + seg*16,
                 A + (size_t)(rowA0+row)*Kd + kb + seg*8);
        }
        #pragma unroll
        for (int i = 0; i < 4; i++){
            int idx = i*256 + tid;
            int row = idx >> 3, seg = idx & 7;
            cp16(base + TILEB + row*AST + seg*16,
                 Bt + (size_t)(colB0+row)*Kd + kb + seg*8);
        }
        CP_COMMIT();
    };

    float acc[4][4][4];
    float* accp = &acc[0][0][0];
    #pragma unroll
    for (int i = 0; i < 64; i++) accp[i] = 0.f;
    uint32_t hacc[4][4][2];
    uint32_t* haccp = &hacc[0][0][0];
    #pragma unroll
    for (int i = 0; i < 32; i++) haccp[i] = 0u;

    loadChunk(0, 0);
    loadChunk(1, 1);
    const uint32_t lrow = (lane & 15);
    const uint32_t lcol = (lane >> 4)*16;
    const uint32_t aOff = (wm*64 + lrow)*AST + lcol;
    const uint32_t bOff = (wn*32 + lrow)*AST + lcol;
    int st = 0;
    for (int c = 0; c < NC; c++){
        if (c + 1 < NC){ CP_WAIT(1); } else { CP_WAIT(0); }
        __syncthreads();
        if (c + 2 < NC){
            int ns = st + 2; if (ns >= NSTAGE) ns -= NSTAGE;
            loadChunk(c+2, ns);
        }
        const uint32_t aRow = sA + st*2*TILEB + aOff;
        const uint32_t bRow = sA + st*2*TILEB + TILEB + bOff;
        #pragma unroll
        for (int k16 = 0; k16 < 4; k16++){
            const uint32_t ko = k16*32;
            uint32_t af[4][4], bf[2][4];
            #pragma unroll
            for (int mi = 0; mi < 4; mi++) ldm4(af[mi], aRow + mi*(16*AST) + ko);
            #pragma unroll
            for (int li = 0; li < 2; li++) ldm4(bf[li], bRow + li*(16*AST) + ko);
            #pragma unroll
            for (int mi = 0; mi < 4; mi++){
                #pragma unroll
                for (int li = 0; li < 2; li++){
                    mma16816h(hacc[mi][li*2+0], af[mi], bf[li][0], bf[li][2]);
                    mma16816h(hacc[mi][li*2+1], af[mi], bf[li][1], bf[li][3]);
                }
            }
        }
        // promote fp16 partials (K=64 window) into fp32 master acc, re-zero
        #pragma unroll
        for (int mi = 0; mi < 4; mi++){
            #pragma unroll
            for (int ni = 0; ni < 4; ni++){
                float2 f01 = __half22float2(*(__half2*)&hacc[mi][ni][0]);
                float2 f23 = __half22float2(*(__half2*)&hacc[mi][ni][1]);
                acc[mi][ni][0] += f01.x; acc[mi][ni][1] += f01.y;
                acc[mi][ni][2] += f23.x; acc[mi][ni][3] += f23.y;
                hacc[mi][ni][0] = 0u;    hacc[mi][ni][1] = 0u;
            }
        }
        if (++st >= NSTAGE) st = 0;
    }

    // epilogue
    const int r0 = rowA0 + wm*64 + (lane>>2);
    const int c0 = colB0 + wn*32 + (lane&3)*2;
    #pragma unroll
    for (int mi = 0; mi < 4; mi++){
        #pragma unroll
        for (int ni = 0; ni < 4; ni++){
            int row = r0 + mi*16, col = c0 + ni*8;
            if (G1){
                __half* hb = g_hbuf;
                *(__half2*)(hb + (size_t)row*Nd + col) =
                    __floats2half2_rn(gelu_f(acc[mi][ni][0]), gelu_f(acc[mi][ni][1]));
                *(__half2*)(hb + (size_t)(row+8)*Nd + col) =
                    __floats2half2_rn(gelu_f(acc[mi][ni][2]), gelu_f(acc[mi][ni][3]));
            } else {
                *(float2*)(g_y + (size_t)row*Nd + col) = make_float2(acc[mi][ni][0], acc[mi][ni][1]);
                *(float2*)(g_y + (size_t)(row+8)*Nd + col) = make_float2(acc[mi][ni][2], acc[mi][ni][3]);
            }
        }
    }
}

__global__ void k_combine(const float* __restrict__ gw, float* __restrict__ out){
    int idx = blockIdx.x*256 + threadIdx.x;
    int t = idx >> 8, c = idx & 255;
    int p0 = g_posOf[2*t], p1 = g_posOf[2*t+1];
    float w0 = gw[2*t], w1v = gw[2*t+1];
    float4 a = ((const float4*)(g_y + (size_t)p0*H_))[c];
    float4 b = ((const float4*)(g_y + (size_t)p1*H_))[c];
    float4 r;
    r.x = w0*a.x + w1v*b.x; r.y = w0*a.y + w1v*b.y;
    r.z = w0*a.z + w1v*b.z; r.w = w0*a.w + w1v*b.w;
    ((float4*)out)[idx] = r;
}

extern "C" void kernel_launch(void* const* d_in, const int* in_sizes, int n_in,
                              void* d_out, int out_size){
    const float* x  = (const float*)d_in[0];
    const float* gw = (const float*)d_in[1];
    const void*  ce = d_in[2];
    const float* w1 = (const float*)d_in[3];
    const float* w2 = (const float*)d_in[4];
    float* out = (float*)d_out;

    cudaFuncSetAttribute(k_gemm<true>,  cudaFuncAttributeMaxDynamicSharedMemorySize, SMEMSZ);
    cudaFuncSetAttribute(k_gemm<false>, cudaFuncAttributeMaxDynamicSharedMemorySize, SMEMSZ);

    dim3 tb(32, 8);
    // order: gemm1 is the 4th launch (ncu -s 5 capture point)
    k_w1t<<<dim3(F_/32, H_/64, E_), tb>>>(w1);
    k_route<<<1, 1024>>>(ce);
    k_gather<<<MAXROWS, 256>>>(x);
    k_gemm<true><<<dim3(F_/128, MAXTILES), 256, SMEMSZ>>>();
    k_w2t<<<dim3(H_/32, F_/64, E_), tb>>>(w2);
    k_gemm<false><<<dim3(H_/128, MAXTILES), 256, SMEMSZ>>>();
    k_combine<<<(T_*H_/4)/256, 256>>>(gw, out);
}

// round 15
// speedup vs baseline: 1.0923x; 1.0923x over previous
#include <cuda_runtime.h>
#include <cuda_fp16.h>
#include <cstdint>

#define S_ 1024
#define B_ 8
#define H_ 1024
#define T_ 8192
#define E_ 8
#define F_ 4096
#define NASSIGN (T_*2)
#define MAXROWS (NASSIGN + E_*128)
#define MAXTILES (MAXROWS/128)
#define W2TILES 16384            // (F/64)*(H/32)*E transpose tiles folded into gemm1
#define W2YEXT  (W2TILES/32)     // extra grid.y rows on gemm1 (512)

// GEMM tiling: CTA 128x128, 8 warps x (64x32), K-chunk 64, 3-stage cp.async
#define KC 64
#define AST 144
#define TILEB (128*AST)
#define NSTAGE 3
#define SMEMSZ (NSTAGE*2*TILEB)   // 110592

// ---- static device scratch ----
__device__ __half g_w1t[(size_t)E_*F_*H_];   // [e][f][h] fp16, k-major rows
__device__ __half g_w2t[(size_t)E_*H_*F_];   // [e][h][f] fp16, k-major rows
__device__ __half g_xh[(size_t)MAXROWS*H_];
__device__ __half g_hbuf[(size_t)MAXROWS*F_];
__device__ int   g_tileExpert[MAXTILES];
__device__ int   g_rowToken[MAXROWS];
__device__ float g_rowCoef[MAXROWS];

__device__ __forceinline__ uint32_t smem_u32(const void* p){
    uint32_t a; asm("{ .reg .u64 t; cvta.to.shared.u64 t, %1; cvt.u32.u64 %0, t; }":"=r"(a):"l"(p)); return a;
}
__device__ __forceinline__ void cp16(uint32_t d, const void* s){
    asm volatile("cp.async.cg.shared.global [%0], [%1], 16;"::"r"(d),"l"(s):"memory");
}
#define CP_COMMIT() asm volatile("cp.async.commit_group;":::"memory")
#define CP_WAIT(n)  asm volatile("cp.async.wait_group %0;"::"n"(n):"memory")

__device__ __forceinline__ void ldm4(uint32_t* r, uint32_t addr){
    asm volatile("ldmatrix.sync.aligned.m8n8.x4.shared.b16 {%0,%1,%2,%3}, [%4];"
        : "=r"(r[0]),"=r"(r[1]),"=r"(r[2]),"=r"(r[3]) : "r"(addr));
}
__device__ __forceinline__ void mma16816(float* c, const uint32_t* a, uint32_t b0, uint32_t b1){
    asm volatile("mma.sync.aligned.m16n8k16.row.col.f32.f16.f16.f32 "
        "{%0,%1,%2,%3},{%4,%5,%6,%7},{%8,%9},{%0,%1,%2,%3};"
        : "+f"(c[0]),"+f"(c[1]),"+f"(c[2]),"+f"(c[3])
        : "r"(a[0]),"r"(a[1]),"r"(a[2]),"r"(a[3]),"r"(b0),"r"(b1));
}

// ---- fused routing (single block); also records per-row gate coefficient ----
__global__ void __launch_bounds__(1024) k_route(const void* __restrict__ ce,
                                                const float* __restrict__ gw){
    __shared__ int scount[E_], scursor[E_], sbase[E_];
    __shared__ int sis32;
    const int tid = threadIdx.x;
    if (tid < E_){ scount[tid]=0; scursor[tid]=0; }
    if (tid == 0) sis32 = 0;
    for (int i = tid; i < MAXROWS; i += 1024){ g_rowToken[i] = -1; g_rowCoef[i] = 0.f; }
    __syncthreads();
    const long long* c64 = (const long long*)ce;
    for (int a = tid; a < NASSIGN/2; a += 1024){
        long long v = c64[a];
        if (v < 0 || v >= E_) sis32 = 1;
    }
    __syncthreads();
    const int is32 = sis32;
    for (int a = tid; a < NASSIGN; a += 1024){
        int e = is32 ? ((const int*)ce)[a] : (int)c64[a];
        atomicAdd(&scount[e], 1);
    }
    __syncthreads();
    if (tid == 0){
        int acc = 0;
        for (int e = 0; e < E_; e++){ sbase[e] = acc; acc += ((scount[e]+127)/128)*128; }
        int t = 0;
        for (int e = 0; e < E_; e++){
            int nt = (scount[e]+127)/128;
            for (int i = 0; i < nt && t < MAXTILES; i++) g_tileExpert[t++] = e;
        }
        for (; t < MAXTILES; t++) g_tileExpert[t] = -1;
    }
    __syncthreads();
    for (int a = tid; a < NASSIGN; a += 1024){
        int e = is32 ? ((const int*)ce)[a] : (int)c64[a];
        int pos = sbase[e] + atomicAdd(&scursor[e], 1);
        g_rowToken[pos] = a >> 1;
        g_rowCoef[pos] = gw[a];
    }
}

__global__ void k_gather(const float* __restrict__ x){
    int pos = blockIdx.x;
    int tok = g_rowToken[pos];
    if (tok < 0) return;
    const float4* s = (const float4*)(x + (size_t)tok*H_);
    __half2* d = (__half2*)(g_xh + (size_t)pos*H_);
    float4 v = s[threadIdx.x];
    d[2*threadIdx.x]   = __floats2half2_rn(v.x, v.y);
    d[2*threadIdx.x+1] = __floats2half2_rn(v.z, v.w);
}

// w1 [E][H][F] -> g_w1t [E][F][H], 64x32 tiles, half2 packed stores
__global__ void k_w1t(const float* __restrict__ w1){
    __shared__ float t[64][33];
    int e = blockIdx.z, hb = blockIdx.y*64, fb = blockIdx.x*32;
    const float* src = w1 + (size_t)e*H_*F_;
    #pragma unroll
    for (int i = threadIdx.y; i < 64; i += 8)
        t[i][threadIdx.x] = src[(size_t)(hb+i)*F_ + fb + threadIdx.x];
    __syncthreads();
    __half2* dst = (__half2*)(g_w1t + (size_t)e*F_*H_);
    #pragma unroll
    for (int i = threadIdx.y; i < 32; i += 8){
        __half2 v = __floats2half2_rn(t[2*threadIdx.x][i], t[2*threadIdx.x+1][i]);
        dst[((size_t)(fb+i)*H_ + hb)/2 + threadIdx.x] = v;
    }
}

__global__ void k_zero(float* __restrict__ out){
    ((float4*)out)[blockIdx.x*256 + threadIdx.x] = make_float4(0.f,0.f,0.f,0.f);
}

__device__ __forceinline__ float gelu_f(float v){
    float c = v + 0.044715f*v*v*v;
    return 0.5f*v*(1.0f + tanhf(0.7978845608028654f*c));
}

// ---- grouped GEMM (proven 485us mainloop): 128x128 CTA, 8 warps x (64x32) ----
// G1: extra grid.y blocks (tile_m >= MAXTILES) transpose w2 -> g_w2t, hidden under GEMM1.
// G2: epilogue scatters coef-weighted fp32 results directly into out via atomicAdd.
template<bool G1>
__global__ void __launch_bounds__(256, 2) k_gemm(const float* __restrict__ wsrc,
                                                 float* __restrict__ out){
    constexpr int Kd = G1 ? H_ : F_;
    constexpr int Nd = G1 ? F_ : H_;
    constexpr int NC = Kd/KC;
    extern __shared__ char smem[];
    const int tile_n = blockIdx.x, tile_m = blockIdx.y;
    const int tid = threadIdx.x;

    if (G1 && tile_m >= MAXTILES){
        // w2 [E][F][H] -> g_w2t [E][H][F], 64(F)x32(H) tile per block
        int i = (tile_m - MAXTILES)*32 + tile_n;      // [0, W2TILES)
        int e2 = i >> 11, r = i & 2047;
        int fb = (r >> 5)*64, hb = (r & 31)*32;
        int tx = tid & 31, ty = tid >> 5;
        float* t = (float*)smem;                      // stride 33
        const float* src = wsrc + (size_t)e2*F_*H_;
        #pragma unroll
        for (int ii = ty; ii < 64; ii += 8)
            t[ii*33 + tx] = src[(size_t)(fb+ii)*H_ + hb + tx];
        __syncthreads();
        __half2* dst = (__half2*)(g_w2t + (size_t)e2*H_*F_);
        #pragma unroll
        for (int ii = ty; ii < 32; ii += 8){
            __half2 v = __floats2half2_rn(t[(2*tx)*33 + ii], t[(2*tx+1)*33 + ii]);
            dst[((size_t)(hb+ii)*F_ + fb)/2 + tx] = v;
        }
        return;
    }

    const int e = g_tileExpert[tile_m];
    if (e < 0) return;
    const __half* A = G1 ? g_xh : g_hbuf;
    const __half* Bt = (G1 ? g_w1t : g_w2t) + (size_t)e*Nd*Kd;
    const int wid = tid>>5, lane = tid&31;
    const int wm = wid & 1, wn = wid >> 1;
    const uint32_t sA = smem_u32(smem);
    const int rowA0 = tile_m*128, colB0 = tile_n*128;

    auto loadChunk = [&](int c, int st){
        const int kb = c*KC;
        const uint32_t base = sA + st*2*TILEB;
        #pragma unroll
        for (int i = 0; i < 4; i++){
            int idx = i*256 + tid;
            int row = idx >> 3, seg = idx & 7;
            cp16(base + row*AST + seg*16,
                 A + (size_t)(rowA0+row)*Kd + kb + seg*8);
        }
        #pragma unroll
        for (int i = 0; i < 4; i++){
            int idx = i*256 + tid;
            int row = idx >> 3, seg = idx & 7;
            cp16(base + TILEB + row*AST + seg*16,
                 Bt + (size_t)(colB0+row)*Kd + kb + seg*8);
        }
        CP_COMMIT();
    };

    float acc[4][4][4];
    float* accp = &acc[0][0][0];
    #pragma unroll
    for (int i = 0; i < 64; i++) accp[i] = 0.f;

    loadChunk(0, 0);
    loadChunk(1, 1);
    const uint32_t lrow = (lane & 15);
    const uint32_t lcol = (lane >> 4)*16;
    const uint32_t aOff = (wm*64 + lrow)*AST + lcol;
    const uint32_t bOff = (wn*32 + lrow)*AST + lcol;
    int st = 0;
    for (int c = 0; c < NC; c++){
        if (c + 1 < NC){ CP_WAIT(1); } else { CP_WAIT(0); }
        __syncthreads();
        if (c + 2 < NC){
            int ns = st + 2; if (ns >= NSTAGE) ns -= NSTAGE;
            loadChunk(c+2, ns);
        }
        const uint32_t aRow = sA + st*2*TILEB + aOff;
        const uint32_t bRow = sA + st*2*TILEB + TILEB + bOff;
        #pragma unroll
        for (int k16 = 0; k16 < 4; k16++){
            const uint32_t ko = k16*32;
            uint32_t af[4][4], bf[2][4];
            #pragma unroll
            for (int mi = 0; mi < 4; mi++) ldm4(af[mi], aRow + mi*(16*AST) + ko);
            #pragma unroll
            for (int li = 0; li < 2; li++) ldm4(bf[li], bRow + li*(16*AST) + ko);
            #pragma unroll
            for (int mi = 0; mi < 4; mi++){
                #pragma unroll
                for (int li = 0; li < 2; li++){
                    mma16816(acc[mi][li*2+0], af[mi], bf[li][0], bf[li][2]);
                    mma16816(acc[mi][li*2+1], af[mi], bf[li][1], bf[li][3]);
                }
            }
        }
        if (++st >= NSTAGE) st = 0;
    }

    // epilogue
    const int r0 = rowA0 + wm*64 + (lane>>2);
    const int c0 = colB0 + wn*32 + (lane&3)*2;
    #pragma unroll
    for (int mi = 0; mi < 4; mi++){
        const int rowA_ = r0 + mi*16, rowB_ = rowA_ + 8;
        if (G1){
            #pragma unroll
            for (int ni = 0; ni < 4; ni++){
                int col = c0 + ni*8;
                __half* hb = g_hbuf;
                *(__half2*)(hb + (size_t)rowA_*Nd + col) =
                    __floats2half2_rn(gelu_f(acc[mi][ni][0]), gelu_f(acc[mi][ni][1]));
                *(__half2*)(hb + (size_t)rowB_*Nd + col) =
                    __floats2half2_rn(gelu_f(acc[mi][ni][2]), gelu_f(acc[mi][ni][3]));
            }
        } else {
            const int tokA = g_rowToken[rowA_], tokB = g_rowToken[rowB_];
            const float cA = g_rowCoef[rowA_],  cB = g_rowCoef[rowB_];
            #pragma unroll
            for (int ni = 0; ni < 4; ni++){
                int col = c0 + ni*8;
                if (tokA >= 0){
                    atomicAdd(&out[(size_t)tokA*H_ + col],     cA*acc[mi][ni][0]);
                    atomicAdd(&out[(size_t)tokA*H_ + col + 1], cA*acc[mi][ni][1]);
                }
                if (tokB >= 0){
                    atomicAdd(&out[(size_t)tokB*H_ + col],     cB*acc[mi][ni][2]);
                    atomicAdd(&out[(size_t)tokB*H_ + col + 1], cB*acc[mi][ni][3]);
                }
            }
        }
    }
}

extern "C" void kernel_launch(void* const* d_in, const int* in_sizes, int n_in,
                              void* d_out, int out_size){
    const float* x  = (const float*)d_in[0];
    const float* gw = (const float*)d_in[1];
    const void*  ce = d_in[2];
    const float* w1 = (const float*)d_in[3];
    const float* w2 = (const float*)d_in[4];
    float* out = (float*)d_out;

    cudaFuncSetAttribute(k_gemm<true>,  cudaFuncAttributeMaxDynamicSharedMemorySize, SMEMSZ);
    cudaFuncSetAttribute(k_gemm<false>, cudaFuncAttributeMaxDynamicSharedMemorySize, SMEMSZ);

    dim3 tb(32, 8);
    // single stream; gemm1 stays the 4th launch (ncu capture point)
    k_w1t<<<dim3(F_/32, H_/64, E_), tb>>>(w1);
    k_route<<<1, 1024>>>(ce, gw);
    k_gather<<<MAXROWS, 256>>>(x);
    k_gemm<true><<<dim3(F_/128, MAXTILES + W2YEXT), 256, SMEMSZ>>>(w2, out);
    k_zero<<<(T_*H_/4)/256, 256>>>(out);
    k_gemm<false><<<dim3(H_/128, MAXTILES), 256, SMEMSZ>>>(w2, out);
}

// round 16
// speedup vs baseline: 1.1468x; 1.0498x over previous
#include <cuda_runtime.h>
#include <cuda_fp16.h>
#include <cstdint>

#define S_ 1024
#define B_ 8
#define H_ 1024
#define T_ 8192
#define E_ 8
#define F_ 4096
#define NASSIGN (T_*2)
#define MAXROWS (NASSIGN + E_*128)
#define MAXTILES (MAXROWS/128)
#define W1TILES 16384            // (F/32)*(H/64)*E
#define W2TILES 16384            // (H/32)*(F/64)*E
#define PREPBLKS (W1TILES + W2TILES + MAXROWS)

// GEMM tiling: CTA 128x128, 8 warps x (64x32), K-chunk 64, 3-stage cp.async
#define KC 64
#define AST 144
#define TILEB (128*AST)
#define NSTAGE 3
#define SMEMSZ (NSTAGE*2*TILEB)   // 110592

// ---- static device scratch ----
__device__ __half g_w1t[(size_t)E_*F_*H_];   // [e][f][h] fp16, k-major rows
__device__ __half g_w2t[(size_t)E_*H_*F_];   // [e][h][f] fp16, k-major rows
__device__ __half g_xh[(size_t)MAXROWS*H_];
__device__ __half g_hbuf[(size_t)MAXROWS*F_];
__device__ int   g_tileExpert[MAXTILES];
__device__ int   g_rowToken[MAXROWS];
__device__ float g_rowCoef[MAXROWS];

__device__ __forceinline__ uint32_t smem_u32(const void* p){
    uint32_t a; asm("{ .reg .u64 t; cvta.to.shared.u64 t, %1; cvt.u32.u64 %0, t; }":"=r"(a):"l"(p)); return a;
}
__device__ __forceinline__ void cp16(uint32_t d, const void* s){
    asm volatile("cp.async.cg.shared.global [%0], [%1], 16;"::"r"(d),"l"(s):"memory");
}
#define CP_COMMIT() asm volatile("cp.async.commit_group;":::"memory")
#define CP_WAIT(n)  asm volatile("cp.async.wait_group %0;"::"n"(n):"memory")

__device__ __forceinline__ void ldm4(uint32_t* r, uint32_t addr){
    asm volatile("ldmatrix.sync.aligned.m8n8.x4.shared.b16 {%0,%1,%2,%3}, [%4];"
        : "=r"(r[0]),"=r"(r[1]),"=r"(r[2]),"=r"(r[3]) : "r"(addr));
}
__device__ __forceinline__ void mma16816(float* c, const uint32_t* a, uint32_t b0, uint32_t b1){
    asm volatile("mma.sync.aligned.m16n8k16.row.col.f32.f16.f16.f32 "
        "{%0,%1,%2,%3},{%4,%5,%6,%7},{%8,%9},{%0,%1,%2,%3};"
        : "+f"(c[0]),"+f"(c[1]),"+f"(c[2]),"+f"(c[3])
        : "r"(a[0]),"r"(a[1]),"r"(a[2]),"r"(a[3]),"r"(b0),"r"(b1));
}

// ---- fused routing (single block); records per-row token + gate coefficient ----
__global__ void __launch_bounds__(1024) k_route(const void* __restrict__ ce,
                                                const float* __restrict__ gw){
    __shared__ int scount[E_], scursor[E_], sbase[E_];
    __shared__ int sis32;
    const int tid = threadIdx.x;
    if (tid < E_){ scount[tid]=0; scursor[tid]=0; }
    if (tid == 0) sis32 = 0;
    for (int i = tid; i < MAXROWS; i += 1024){ g_rowToken[i] = -1; g_rowCoef[i] = 0.f; }
    __syncthreads();
    const long long* c64 = (const long long*)ce;
    for (int a = tid; a < NASSIGN/2; a += 1024){
        long long v = c64[a];
        if (v < 0 || v >= E_) sis32 = 1;
    }
    __syncthreads();
    const int is32 = sis32;
    for (int a = tid; a < NASSIGN; a += 1024){
        int e = is32 ? ((const int*)ce)[a] : (int)c64[a];
        atomicAdd(&scount[e], 1);
    }
    __syncthreads();
    if (tid == 0){
        int acc = 0;
        for (int e = 0; e < E_; e++){ sbase[e] = acc; acc += ((scount[e]+127)/128)*128; }
        int t = 0;
        for (int e = 0; e < E_; e++){
            int nt = (scount[e]+127)/128;
            for (int i = 0; i < nt && t < MAXTILES; i++) g_tileExpert[t++] = e;
        }
        for (; t < MAXTILES; t++) g_tileExpert[t] = -1;
    }
    __syncthreads();
    for (int a = tid; a < NASSIGN; a += 1024){
        int e = is32 ? ((const int*)ce)[a] : (int)c64[a];
        int pos = sbase[e] + atomicAdd(&scursor[e], 1);
        g_rowToken[pos] = a >> 1;
        g_rowCoef[pos] = gw[a];
    }
}

// ---- fused prep: w1 transpose + w2 transpose + token gather in one grid ----
// All three are independent given routing; small smem -> full occupancy, max DRAM MLP.
__global__ void __launch_bounds__(256) k_prep(const float* __restrict__ w1,
                                              const float* __restrict__ w2,
                                              const float* __restrict__ x){
    __shared__ float t[64][33];
    const int bid = blockIdx.x;
    const int tid = threadIdx.x, tx = tid & 31, ty = tid >> 5;
    if (bid < W1TILES){
        // w1 [E][H][F] -> g_w1t [E][F][H]; tile 64(h) x 32(f)
        int e = bid >> 11, r = bid & 2047;
        int fb = (r & 127)*32, hb = (r >> 7)*64;
        const float* src = w1 + (size_t)e*H_*F_;
        #pragma unroll
        for (int i = ty; i < 64; i += 8)
            t[i][tx] = src[(size_t)(hb+i)*F_ + fb + tx];
        __syncthreads();
        __half2* dst = (__half2*)(g_w1t + (size_t)e*F_*H_);
        #pragma unroll
        for (int i = ty; i < 32; i += 8){
            __half2 v = __floats2half2_rn(t[2*tx][i], t[2*tx+1][i]);
            dst[((size_t)(fb+i)*H_ + hb)/2 + tx] = v;
        }
    } else if (bid < W1TILES + W2TILES){
        // w2 [E][F][H] -> g_w2t [E][H][F]; tile 64(f) x 32(h)
        int i0 = bid - W1TILES;
        int e = i0 >> 11, r = i0 & 2047;
        int fb = (r >> 5)*64, hb = (r & 31)*32;
        const float* src = w2 + (size_t)e*F_*H_;
        #pragma unroll
        for (int i = ty; i < 64; i += 8)
            t[i][tx] = src[(size_t)(fb+i)*H_ + hb + tx];
        __syncthreads();
        __half2* dst = (__half2*)(g_w2t + (size_t)e*H_*F_);
        #pragma unroll
        for (int i = ty; i < 32; i += 8){
            __half2 v = __floats2half2_rn(t[2*tx][i], t[2*tx+1][i]);
            dst[((size_t)(hb+i)*F_ + fb)/2 + tx] = v;
        }
    } else {
        // token gather fp32 -> fp16 per padded row
        int pos = bid - (W1TILES + W2TILES);
        int tok = g_rowToken[pos];
        if (tok < 0) return;
        const float4* s = (const float4*)(x + (size_t)tok*H_);
        __half2* d = (__half2*)(g_xh + (size_t)pos*H_);
        float4 v = s[tid];
        d[2*tid]   = __floats2half2_rn(v.x, v.y);
        d[2*tid+1] = __floats2half2_rn(v.z, v.w);
    }
}

__device__ __forceinline__ float gelu_f(float v){
    float c = v + 0.044715f*v*v*v;
    return 0.5f*v*(1.0f + tanhf(0.7978845608028654f*c));
}

// ---- grouped GEMM (proven 485us mainloop): 128x128 CTA, 8 warps x (64x32) ----
// G1: each block also zeroes its slice of out (gemm2's atomics need zeroed output).
// G2: epilogue scatters coef-weighted fp32 results directly into out via atomicAdd.
template<bool G1>
__global__ void __launch_bounds__(256, 2) k_gemm(float* __restrict__ out){
    constexpr int Kd = G1 ? H_ : F_;
    constexpr int Nd = G1 ? F_ : H_;
    constexpr int NC = Kd/KC;
    extern __shared__ char smem[];
    const int tile_n = blockIdx.x, tile_m = blockIdx.y;
    const int tid = threadIdx.x;

    if (G1){
        // zero out's slice (fire-and-forget; ordered before gemm2 by kernel boundary)
        const int bid = tile_m*gridDim.x + tile_n;
        const int stride = gridDim.x*gridDim.y*256;
        float4* o4 = (float4*)out;
        for (int i = bid*256 + tid; i < T_*H_/4; i += stride)
            o4[i] = make_float4(0.f, 0.f, 0.f, 0.f);
    }

    const int e = g_tileExpert[tile_m];
    if (e < 0) return;
    const __half* A = G1 ? g_xh : g_hbuf;
    const __half* Bt = (G1 ? g_w1t : g_w2t) + (size_t)e*Nd*Kd;
    const int wid = tid>>5, lane = tid&31;
    const int wm = wid & 1, wn = wid >> 1;
    const uint32_t sA = smem_u32(smem);
    const int rowA0 = tile_m*128, colB0 = tile_n*128;

    auto loadChunk = [&](int c, int st){
        const int kb = c*KC;
        const uint32_t base = sA + st*2*TILEB;
        #pragma unroll
        for (int i = 0; i < 4; i++){
            int idx = i*256 + tid;
            int row = idx >> 3, seg = idx & 7;
            cp16(base + row*AST + seg*16,
                 A + (size_t)(rowA0+row)*Kd + kb + seg*8);
        }
        #pragma unroll
        for (int i = 0; i < 4; i++){
            int idx = i*256 + tid;
            int row = idx >> 3, seg = idx & 7;
            cp16(base + TILEB + row*AST + seg*16,
                 Bt + (size_t)(colB0+row)*Kd + kb + seg*8);
        }
        CP_COMMIT();
    };

    float acc[4][4][4];
    float* accp = &acc[0][0][0];
    #pragma unroll
    for (int i = 0; i < 64; i++) accp[i] = 0.f;

    loadChunk(0, 0);
    loadChunk(1, 1);
    const uint32_t lrow = (lane & 15);
    const uint32_t lcol = (lane >> 4)*16;
    const uint32_t aOff = (wm*64 + lrow)*AST + lcol;
    const uint32_t bOff = (wn*32 + lrow)*AST + lcol;
    int st = 0;
    for (int c = 0; c < NC; c++){
        if (c + 1 < NC){ CP_WAIT(1); } else { CP_WAIT(0); }
        __syncthreads();
        if (c + 2 < NC){
            int ns = st + 2; if (ns >= NSTAGE) ns -= NSTAGE;
            loadChunk(c+2, ns);
        }
        const uint32_t aRow = sA + st*2*TILEB + aOff;
        const uint32_t bRow = sA + st*2*TILEB + TILEB + bOff;
        #pragma unroll
        for (int k16 = 0; k16 < 4; k16++){
            const uint32_t ko = k16*32;
            uint32_t af[4][4], bf[2][4];
            #pragma unroll
            for (int mi = 0; mi < 4; mi++) ldm4(af[mi], aRow + mi*(16*AST) + ko);
            #pragma unroll
            for (int li = 0; li < 2; li++) ldm4(bf[li], bRow + li*(16*AST) + ko);
            #pragma unroll
            for (int mi = 0; mi < 4; mi++){
                #pragma unroll
                for (int li = 0; li < 2; li++){
                    mma16816(acc[mi][li*2+0], af[mi], bf[li][0], bf[li][2]);
                    mma16816(acc[mi][li*2+1], af[mi], bf[li][1], bf[li][3]);
                }
            }
        }
        if (++st >= NSTAGE) st = 0;
    }

    // epilogue
    const int r0 = rowA0 + wm*64 + (lane>>2);
    const int c0 = colB0 + wn*32 + (lane&3)*2;
    #pragma unroll
    for (int mi = 0; mi < 4; mi++){
        const int rowA_ = r0 + mi*16, rowB_ = rowA_ + 8;
        if (G1){
            #pragma unroll
            for (int ni = 0; ni < 4; ni++){
                int col = c0 + ni*8;
                __half* hb = g_hbuf;
                *(__half2*)(hb + (size_t)rowA_*Nd + col) =
                    __floats2half2_rn(gelu_f(acc[mi][ni][0]), gelu_f(acc[mi][ni][1]));
                *(__half2*)(hb + (size_t)rowB_*Nd + col) =
                    __floats2half2_rn(gelu_f(acc[mi][ni][2]), gelu_f(acc[mi][ni][3]));
            }
        } else {
            const int tokA = g_rowToken[rowA_], tokB = g_rowToken[rowB_];
            const float cA = g_rowCoef[rowA_],  cB = g_rowCoef[rowB_];
            #pragma unroll
            for (int ni = 0; ni < 4; ni++){
                int col = c0 + ni*8;
                if (tokA >= 0){
                    atomicAdd(&out[(size_t)tokA*H_ + col],     cA*acc[mi][ni][0]);
                    atomicAdd(&out[(size_t)tokA*H_ + col + 1], cA*acc[mi][ni][1]);
                }
                if (tokB >= 0){
                    atomicAdd(&out[(size_t)tokB*H_ + col],     cB*acc[mi][ni][2]);
                    atomicAdd(&out[(size_t)tokB*H_ + col + 1], cB*acc[mi][ni][3]);
                }
            }
        }
    }
}

extern "C" void kernel_launch(void* const* d_in, const int* in_sizes, int n_in,
                              void* d_out, int out_size){
    const float* x  = (const float*)d_in[0];
    const float* gw = (const float*)d_in[1];
    const void*  ce = d_in[2];
    const float* w1 = (const float*)d_in[3];
    const float* w2 = (const float*)d_in[4];
    float* out = (float*)d_out;

    cudaFuncSetAttribute(k_gemm<true>,  cudaFuncAttributeMaxDynamicSharedMemorySize, SMEMSZ);
    cudaFuncSetAttribute(k_gemm<false>, cudaFuncAttributeMaxDynamicSharedMemorySize, SMEMSZ);

    k_route<<<1, 1024>>>(ce, gw);
    k_prep<<<PREPBLKS, 256>>>(w1, w2, x);
    k_gemm<true><<<dim3(F_/128, MAXTILES), 256, SMEMSZ>>>(out);
    k_gemm<false><<<dim3(H_/128, MAXTILES), 256, SMEMSZ>>>(out);
}